// round 9
// baseline (speedup 1.0000x reference)
#include <cuda_runtime.h>
#include <cstdint>

// Problem constants
#define Bb     8
#define Ll     4096
#define Dd     1024
#define Hh     16
#define BLK    4
#define HDIM   64
#define MTOT   (Bb*Ll)        // 32768
#define NQKV   (3*Dd)         // 3072

// Scratch (no cudaMalloc allowed)
__device__ float g_qkv[100663296];  // 32768 * 3072
__device__ float g_o[33554432];     // attention out (tf32-rounded)
__device__ float g_xt[33554432];    // x pre-rounded
__device__ float g_wqt[3145728];    // W_qkv transposed [3072][1024], tf32-rounded
__device__ float g_wpt[1048576];    // W_proj transposed [1024][1024], tf32-rounded

// ---------------------------------------------------------------------------
__device__ __forceinline__ uint32_t smem_u32(const void* p) {
    uint32_t a;
    asm("{ .reg .u64 t; cvta.to.shared.u64 t, %1; cvt.u32.u64 %0, t; }" : "=r"(a) : "l"(p));
    return a;
}

__device__ __forceinline__ float tf32r(float f) {
    uint32_t r;
    asm("cvt.rna.tf32.f32 %0, %1;" : "=r"(r) : "f"(f));
    return __uint_as_float(r);
}

__device__ __forceinline__ void cpasync16(uint32_t dst, const void* src) {
    asm volatile("cp.async.cg.shared.global [%0], [%1], 16;" :: "r"(dst), "l"(src));
}
#define CP_COMMIT() asm volatile("cp.async.commit_group;" ::: "memory")
#define CP_WAIT1()  asm volatile("cp.async.wait_group 1;" ::: "memory")

__device__ __forceinline__ void mma_tf32(float c[4], const uint32_t a[4], const uint32_t b[2]) {
    asm volatile(
        "mma.sync.aligned.m16n8k8.row.col.f32.tf32.tf32.f32 "
        "{%0,%1,%2,%3}, {%4,%5,%6,%7}, {%8,%9}, {%0,%1,%2,%3};\n"
        : "+f"(c[0]), "+f"(c[1]), "+f"(c[2]), "+f"(c[3])
        : "r"(a[0]), "r"(a[1]), "r"(a[2]), "r"(a[3]),
          "r"(b[0]), "r"(b[1]));
}

// ---------------------------------------------------------------------------
// Prologue kernels
// ---------------------------------------------------------------------------
__global__ __launch_bounds__(256)
void tf32_round_kernel(const float4* __restrict__ in, float4* __restrict__ out, int n4)
{
    int i = blockIdx.x * blockDim.x + threadIdx.x;
    int stride = gridDim.x * blockDim.x;
    for (; i < n4; i += stride) {
        float4 v = in[i];
        v.x = tf32r(v.x); v.y = tf32r(v.y);
        v.z = tf32r(v.z); v.w = tf32r(v.w);
        out[i] = v;
    }
}

// out[N][K] = tf32_round(in[K][N]^T). 32x32 tiles, 32x8 threads.
__global__ __launch_bounds__(256)
void transpose_tf32_kernel(const float* __restrict__ in, float* __restrict__ out,
                           int K, int N)
{
    __shared__ float t[32][33];
    const int n0 = blockIdx.x * 32;
    const int k0 = blockIdx.y * 32;
    const int tx = threadIdx.x & 31;
    const int ty = threadIdx.x >> 5;   // 0..7
#pragma unroll
    for (int j = 0; j < 4; ++j)
        t[ty + j * 8][tx] = in[(size_t)(k0 + ty + j * 8) * N + n0 + tx];
    __syncthreads();
#pragma unroll
    for (int j = 0; j < 4; ++j)
        out[(size_t)(n0 + ty + j * 8) * K + k0 + tx] = tf32r(t[tx][ty + j * 8]);
}

// ---------------------------------------------------------------------------
// TF32 GEMM via mma.sync. CTA 128(M) x 128(N), BK=32, 256 threads, 8 warps of
// 32(M) x 64(N), 2 CTAs/SM. 3-stage cp.async pipeline.
// Per k-step: 2 A-LDSM.x4 + 4 B-LDSM.x4 -> 16 MMAs (1.5 issues/MMA).
// A [M][K] row-major, Bt [N][K] row-major — same smem layout (128B rows,
// SW128 swizzle), all fragments via ldmatrix.x4.
// Requires M%128==0, N%128==0, K%32==0, K>=64.
// ---------------------------------------------------------------------------
#define A_TILE  16384
#define B_TILE  16384
#define STAGE_B (A_TILE + B_TILE)      // 32768
#define STAGES  3
#define GEMM_SMEM (STAGES * STAGE_B)   // 98304
#define BKC 32

__global__ __launch_bounds__(256, 2)
void gemm_mma_kernel(const float* __restrict__ A, const float* __restrict__ Bt,
                     const float* __restrict__ bias, float* __restrict__ C,
                     int N, int K)
{
    extern __shared__ char dsm[];
    const uint32_t sbase = smem_u32(dsm);

    const int tid  = threadIdx.x;
    const int wid  = tid >> 5;
    const int lane = tid & 31;
    const int warpM = wid & 3;       // 4 groups of 32 rows
    const int warpN = wid >> 2;      // 2 groups of 64 cols

    const int m0 = blockIdx.y * 128;
    const int n0 = blockIdx.x * 128;
    const int NC = K >> 5;

    // ---- staging: 64-bit bases + 32-bit byte offsets; 4 A + 4 B per thread ----
    const char* Ab = (const char*)A;
    const char* Bb_ = (const char*)Bt;
    uint32_t rel[4];
    uint32_t aOff[4], bOff[4];
#pragma unroll
    for (int it = 0; it < 4; ++it) {
        int idx = tid + it * 256;            // 0..1023
        int r = idx >> 3, k16 = idx & 7;
        rel[it] = r * 128 + (((k16 ^ (r & 7)) << 4));
        aOff[it] = (uint32_t)((m0 + r) * K + k16 * 4) * 4u;
        bOff[it] = (uint32_t)((n0 + r) * K + k16 * 4) * 4u;
    }

    auto stageF = [&](int s) {
        uint32_t aBase = sbase + s * STAGE_B;
        uint32_t bBase = aBase + A_TILE;
#pragma unroll
        for (int it = 0; it < 4; ++it) {
            cpasync16(aBase + rel[it], Ab + aOff[it]);
            aOff[it] += BKC * 4;
        }
#pragma unroll
        for (int it = 0; it < 4; ++it) {
            cpasync16(bBase + rel[it], Bb_ + bOff[it]);
            bOff[it] += BKC * 4;
        }
    };

    stageF(0); CP_COMMIT();
    stageF(1); CP_COMMIT();

    // ---- fragment address precompute ----
    const int r8  = lane & 7;
    const int sel = lane >> 3;                 // 0..3
    const int rowAdd = r8 + ((sel & 2) << 2);  // +8 rows for mats 2,3
    const int colAdd = sel & 1;                // +1 16B col for mats 1,3
    uint32_t colPart[4];
#pragma unroll
    for (int ks = 0; ks < 4; ++ks)
        colPart[ks] = (uint32_t)(((2 * ks + colAdd) ^ r8) << 4);

    uint32_t aRow[2], bRow[4];
#pragma unroll
    for (int g = 0; g < 2; ++g)
        aRow[g] = (uint32_t)(warpM * 32 + g * 16 + rowAdd) * 128;
#pragma unroll
    for (int j = 0; j < 4; ++j)
        bRow[j] = (uint32_t)(warpN * 64 + j * 16 + rowAdd) * 128 + A_TILE;

    float acc[2][8][4];
#pragma unroll
    for (int mt = 0; mt < 2; ++mt)
#pragma unroll
        for (int nt = 0; nt < 8; ++nt)
#pragma unroll
            for (int r = 0; r < 4; ++r) acc[mt][nt][r] = 0.0f;

    uint32_t aF[2][4], bF[8][2];

    for (int c = 0; c < NC; ++c) {
        CP_WAIT1();
        __syncthreads();
        if (c + 2 < NC) stageF((c + 2) % 3);
        CP_COMMIT();

        const uint32_t sB = sbase + (c % 3) * STAGE_B;

#pragma unroll
        for (int ks = 0; ks < 4; ++ks) {
            uint32_t cp = colPart[ks];
#pragma unroll
            for (int mt = 0; mt < 2; ++mt) {
                uint32_t r0, r1, r2, r3;
                asm volatile("ldmatrix.sync.aligned.m8n8.x4.shared.b16 {%0,%1,%2,%3}, [%4];"
                             : "=r"(r0), "=r"(r1), "=r"(r2), "=r"(r3)
                             : "r"(sB + aRow[mt] + cp));
                aF[mt][0] = r0; aF[mt][1] = r2;
                aF[mt][2] = r1; aF[mt][3] = r3;
            }
#pragma unroll
            for (int j = 0; j < 4; ++j) {
                uint32_t r0, r1, r2, r3;
                asm volatile("ldmatrix.sync.aligned.m8n8.x4.shared.b16 {%0,%1,%2,%3}, [%4];"
                             : "=r"(r0), "=r"(r1), "=r"(r2), "=r"(r3)
                             : "r"(sB + bRow[j] + cp));
                bF[j * 2][0]     = r0; bF[j * 2][1]     = r1;
                bF[j * 2 + 1][0] = r2; bF[j * 2 + 1][1] = r3;
            }
#pragma unroll
            for (int mt = 0; mt < 2; ++mt)
#pragma unroll
                for (int nt = 0; nt < 8; ++nt)
                    mma_tf32(acc[mt][nt], aF[mt], bF[nt]);
        }
    }

    // ---- epilogue: bias + STG.64 ----
    const int col0 = n0 + warpN * 64 + 2 * (lane & 3);
    float2 bv[8];
#pragma unroll
    for (int nt = 0; nt < 8; ++nt)
        bv[nt] = *(const float2*)(bias + col0 + nt * 8);

    const int row0 = m0 + warpM * 32 + (lane >> 2);
#pragma unroll
    for (int mt = 0; mt < 2; ++mt) {
        int r = row0 + mt * 16;
#pragma unroll
        for (int nt = 0; nt < 8; ++nt) {
            int cc = col0 + nt * 8;
            float2 v0, v1;
            v0.x = acc[mt][nt][0] + bv[nt].x;
            v0.y = acc[mt][nt][1] + bv[nt].y;
            v1.x = acc[mt][nt][2] + bv[nt].x;
            v1.y = acc[mt][nt][3] + bv[nt].y;
            *(float2*)(C + (size_t)r * N + cc)       = v0;
            *(float2*)(C + (size_t)(r + 8) * N + cc) = v1;
        }
    }
}

// ---------------------------------------------------------------------------
// Block attention: one warp per (b, h, block). BS=4, d=64.
// Output rounded to tf32 bits (feeds proj GEMM).
// ---------------------------------------------------------------------------
__global__ __launch_bounds__(256)
void block_attn_kernel(const float* __restrict__ qkv, float* __restrict__ o)
{
    const int gwarp = (blockIdx.x * blockDim.x + threadIdx.x) >> 5;
    const int lane  = threadIdx.x & 31;

    const int nb = gwarp & 1023;
    const int bh = gwarp >> 10;
    const int h  = bh & 15;
    const int b  = bh >> 4;
    const int l0 = nb * BLK;

    const size_t rowBase = ((size_t)(b * Ll + l0)) * NQKV + h * 192;

    float2 q[4], k[4], v[4];
#pragma unroll
    for (int i = 0; i < 4; ++i) {
        const float* p = qkv + rowBase + (size_t)i * NQKV + 2 * lane;
        q[i] = *(const float2*)(p);
        k[i] = *(const float2*)(p + 64);
        v[i] = *(const float2*)(p + 128);
    }

    float s[4][4];
#pragma unroll
    for (int i = 0; i < 4; ++i)
#pragma unroll
        for (int j = 0; j < 4; ++j)
            s[i][j] = fmaf(q[i].y, k[j].y, q[i].x * k[j].x);

#pragma unroll
    for (int i = 0; i < 4; ++i)
#pragma unroll
        for (int j = 0; j < 4; ++j)
#pragma unroll
            for (int off = 16; off > 0; off >>= 1)
                s[i][j] += __shfl_xor_sync(0xffffffffu, s[i][j], off);

    const float scale = 0.125f;
    float2 outv[4];
#pragma unroll
    for (int i = 0; i < 4; ++i) {
        float t0 = s[i][0] * scale, t1 = s[i][1] * scale;
        float t2 = s[i][2] * scale, t3 = s[i][3] * scale;
        float m = fmaxf(fmaxf(t0, t1), fmaxf(t2, t3));
        float e0 = __expf(t0 - m), e1 = __expf(t1 - m);
        float e2 = __expf(t2 - m), e3 = __expf(t3 - m);
        float inv = 1.0f / (e0 + e1 + e2 + e3);
        float p0 = e0 * inv, p1 = e1 * inv, p2 = e2 * inv, p3 = e3 * inv;
        float ox = p0 * v[0].x; ox = fmaf(p1, v[1].x, ox);
        ox = fmaf(p2, v[2].x, ox); ox = fmaf(p3, v[3].x, ox);
        float oy = p0 * v[0].y; oy = fmaf(p1, v[1].y, oy);
        oy = fmaf(p2, v[2].y, oy); oy = fmaf(p3, v[3].y, oy);
        outv[i].x = tf32r(ox); outv[i].y = tf32r(oy);
    }

    const size_t obase = ((size_t)(b * Ll + l0)) * Dd + h * HDIM + 2 * lane;
#pragma unroll
    for (int i = 0; i < 4; ++i)
        *(float2*)(o + obase + (size_t)i * Dd) = outv[i];
}

// ---------------------------------------------------------------------------
extern "C" void kernel_launch(void* const* d_in, const int* in_sizes, int n_in,
                              void* d_out, int out_size)
{
    const float* x     = (const float*)d_in[0];
    const float* Wqkv  = (const float*)d_in[1];
    const float* bqkv  = (const float*)d_in[2];
    const float* Wproj = (const float*)d_in[3];
    const float* bproj = (const float*)d_in[4];
    float* out = (float*)d_out;

    float *qkv, *ob, *xt, *wqt, *wpt;
    cudaGetSymbolAddress((void**)&qkv, g_qkv);
    cudaGetSymbolAddress((void**)&ob,  g_o);
    cudaGetSymbolAddress((void**)&xt,  g_xt);
    cudaGetSymbolAddress((void**)&wqt, g_wqt);
    cudaGetSymbolAddress((void**)&wpt, g_wpt);

    cudaFuncSetAttribute(gemm_mma_kernel,
                         cudaFuncAttributeMaxDynamicSharedMemorySize, GEMM_SMEM);

    // 0) pre-round x; transpose+round weights (Wt[N][K])
    tf32_round_kernel<<<8192, 256>>>((const float4*)x, (float4*)xt, MTOT * Dd / 4);
    {
        dim3 g1(NQKV / 32, Dd / 32);
        transpose_tf32_kernel<<<g1, 256>>>(Wqkv, wqt, Dd, NQKV);
        dim3 g2(Dd / 32, Dd / 32);
        transpose_tf32_kernel<<<g2, 256>>>(Wproj, wpt, Dd, Dd);
    }

    // 1) qkv = x @ W_qkv + b_qkv   (32768 x 3072 x 1024)
    {
        dim3 grid(NQKV / 128, MTOT / 128);
        gemm_mma_kernel<<<grid, 256, GEMM_SMEM>>>(xt, wqt, bqkv, qkv, NQKV, Dd);
    }

    // 2) block attention (tf32-rounded output)
    {
        int nwarps = Bb * Hh * (Ll / BLK);
        block_attn_kernel<<<nwarps / 8, 256>>>(qkv, ob);
    }

    // 3) out = o @ W_proj + b_proj  (32768 x 1024 x 1024)
    {
        dim3 grid(Dd / 128, MTOT / 128);
        gemm_mma_kernel<<<grid, 256, GEMM_SMEM>>>(ob, wpt, bproj, out, Dd, Dd);
    }
}

// round 10
// speedup vs baseline: 1.8224x; 1.8224x over previous
#include <cuda_runtime.h>
#include <cuda_fp16.h>
#include <cstdint>

// Problem constants
#define Bb     8
#define Ll     4096
#define Dd     1024
#define Hh     16
#define BLK    4
#define HDIM   64
#define MTOT   (Bb*Ll)        // 32768
#define NQKV   (3*Dd)         // 3072

// Scratch (no cudaMalloc allowed)
__device__ float  g_qkv[100663296];  // 32768 * 3072 (f32)
__device__ __half g_oh[33554432];    // attention out, fp16
__device__ __half g_xh[33554432];    // x in fp16
__device__ __half g_wqh[3145728];    // W_qkv^T [3072][1024] fp16
__device__ __half g_wph[1048576];    // W_proj^T [1024][1024] fp16

// ---------------------------------------------------------------------------
__device__ __forceinline__ uint32_t smem_u32(const void* p) {
    uint32_t a;
    asm("{ .reg .u64 t; cvta.to.shared.u64 t, %1; cvt.u32.u64 %0, t; }" : "=r"(a) : "l"(p));
    return a;
}

__device__ __forceinline__ void cpasync16(uint32_t dst, const void* src) {
    asm volatile("cp.async.cg.shared.global [%0], [%1], 16;" :: "r"(dst), "l"(src));
}
#define CP_COMMIT() asm volatile("cp.async.commit_group;" ::: "memory")
#define CP_WAIT1()  asm volatile("cp.async.wait_group 1;" ::: "memory")

// fp16 MMA, f32 accumulate: m16n8k16
__device__ __forceinline__ void mma_f16(float c[4], const uint32_t a[4], const uint32_t b[2]) {
    asm volatile(
        "mma.sync.aligned.m16n8k16.row.col.f32.f16.f16.f32 "
        "{%0,%1,%2,%3}, {%4,%5,%6,%7}, {%8,%9}, {%0,%1,%2,%3};\n"
        : "+f"(c[0]), "+f"(c[1]), "+f"(c[2]), "+f"(c[3])
        : "r"(a[0]), "r"(a[1]), "r"(a[2]), "r"(a[3]),
          "r"(b[0]), "r"(b[1]));
}

// ---------------------------------------------------------------------------
// Prologue kernels
// ---------------------------------------------------------------------------
__global__ __launch_bounds__(256)
void f2h_kernel(const float4* __restrict__ in, uint2* __restrict__ out, int n4)
{
    int i = blockIdx.x * blockDim.x + threadIdx.x;
    int stride = gridDim.x * blockDim.x;
    for (; i < n4; i += stride) {
        float4 v = in[i];
        __half2 lo = __floats2half2_rn(v.x, v.y);
        __half2 hi = __floats2half2_rn(v.z, v.w);
        uint2 u;
        u.x = *reinterpret_cast<uint32_t*>(&lo);
        u.y = *reinterpret_cast<uint32_t*>(&hi);
        out[i] = u;
    }
}

// out[N][K] = fp16(in[K][N]^T). 32x32 tiles, 256 threads.
__global__ __launch_bounds__(256)
void transpose_h_kernel(const float* __restrict__ in, __half* __restrict__ out,
                        int K, int N)
{
    __shared__ float t[32][33];
    const int n0 = blockIdx.x * 32;
    const int k0 = blockIdx.y * 32;
    const int tx = threadIdx.x & 31;
    const int ty = threadIdx.x >> 5;   // 0..7
#pragma unroll
    for (int j = 0; j < 4; ++j)
        t[ty + j * 8][tx] = in[(size_t)(k0 + ty + j * 8) * N + n0 + tx];
    __syncthreads();
#pragma unroll
    for (int j = 0; j < 4; ++j)
        out[(size_t)(n0 + ty + j * 8) * K + k0 + tx] = __float2half_rn(t[tx][ty + j * 8]);
}

// ---------------------------------------------------------------------------
// FP16 GEMM via mma.sync m16n8k16, f32 accum. CTA 128(M) x 64(N), BK=64,
// 256 threads, 8 warps of 32x32, 3 CTAs/SM. 3-stage cp.async pipeline.
// A [M][K] fp16 row-major, Bt [N][K] fp16 row-major — same smem layout:
// rows of 128B (64 halves), SW128 swizzle, fragments via ldmatrix.x4 (native).
// C output f32 (+bias). Requires M%128==0, N%64==0, K%64==0, K>=128.
// ---------------------------------------------------------------------------
#define A_TILE  16384
#define B_TILE  8192
#define STAGE_B (A_TILE + B_TILE)      // 24576
#define STAGES  3
#define GEMM_SMEM (STAGES * STAGE_B)   // 73728
#define BKC 64

__global__ __launch_bounds__(256, 3)
void gemm_hmma_kernel(const __half* __restrict__ A, const __half* __restrict__ Bt,
                      const float* __restrict__ bias, float* __restrict__ C,
                      int N, int K)
{
    extern __shared__ char dsm[];
    const uint32_t sbase = smem_u32(dsm);

    const int tid  = threadIdx.x;
    const int wid  = tid >> 5;
    const int lane = tid & 31;
    const int warpM = wid & 3;       // 4 groups of 32 rows
    const int warpN = wid >> 2;      // 2 groups of 32 cols

    const int m0 = blockIdx.y * 128;
    const int n0 = blockIdx.x * 64;
    const int NC = K >> 6;           // chunks of 64 halves (128B rows)

    // ---- staging: 64-bit bases + 32-bit byte offsets ----
    const char* Ab  = (const char*)A;
    const char* Bb_ = (const char*)Bt;
    uint32_t aRel[4], bRel[2];
    uint32_t aOff[4], bOff[2];
#pragma unroll
    for (int it = 0; it < 4; ++it) {
        int idx = tid + it * 256;            // 0..1023
        int r = idx >> 3, k16 = idx & 7;     // row 0..127, 16B chunk 0..7
        aRel[it] = r * 128 + (((k16 ^ (r & 7)) << 4));
        aOff[it] = (uint32_t)((m0 + r) * K + k16 * 8) * 2u;
    }
#pragma unroll
    for (int it = 0; it < 2; ++it) {
        int idx = tid + it * 256;            // 0..511
        int r = idx >> 3, k16 = idx & 7;
        bRel[it] = r * 128 + (((k16 ^ (r & 7)) << 4));
        bOff[it] = (uint32_t)((n0 + r) * K + k16 * 8) * 2u;
    }

    auto stageF = [&](int s) {
        uint32_t aBase = sbase + s * STAGE_B;
        uint32_t bBase = aBase + A_TILE;
#pragma unroll
        for (int it = 0; it < 4; ++it) {
            cpasync16(aBase + aRel[it], Ab + aOff[it]);
            aOff[it] += BKC * 2;
        }
#pragma unroll
        for (int it = 0; it < 2; ++it) {
            cpasync16(bBase + bRel[it], Bb_ + bOff[it]);
            bOff[it] += BKC * 2;
        }
    };

    stageF(0); CP_COMMIT();
    stageF(1); CP_COMMIT();

    // ---- fragment address precompute (fp16 16816 mapping) ----
    // x4: lanes 0-7 -> rows 0-7 (k-lo), 8-15 -> rows 8-15 (k-lo),
    //     16-23 -> rows 0-7 (k-hi, +16B), 24-31 -> rows 8-15 (k-hi)
    const int r8  = lane & 7;
    const int sel = lane >> 3;                 // 0..3
    const int rowAdd = r8 + ((sel & 1) << 3);  // +8 rows for mats 1,3
    const int colAdd = sel >> 1;               // +1 16B col for mats 2,3
    uint32_t colPart[4];
#pragma unroll
    for (int ks = 0; ks < 4; ++ks)             // k-step = 16 halves = 2 x 16B
        colPart[ks] = (uint32_t)(((2 * ks + colAdd) ^ r8) << 4);

    uint32_t aRow[2], bRow[2];
#pragma unroll
    for (int g = 0; g < 2; ++g) {
        aRow[g] = (uint32_t)(warpM * 32 + g * 16 + rowAdd) * 128;
        bRow[g] = (uint32_t)(warpN * 32 + g * 16 + rowAdd) * 128 + A_TILE;
    }

    float acc[2][4][4];
#pragma unroll
    for (int mt = 0; mt < 2; ++mt)
#pragma unroll
        for (int nt = 0; nt < 4; ++nt)
#pragma unroll
            for (int r = 0; r < 4; ++r) acc[mt][nt][r] = 0.0f;

    uint32_t aF[2][4], bF[4][2];

    for (int c = 0; c < NC; ++c) {
        CP_WAIT1();
        __syncthreads();
        if (c + 2 < NC) stageF((c + 2) % 3);
        CP_COMMIT();

        const uint32_t sB = sbase + (c % 3) * STAGE_B;

#pragma unroll
        for (int ks = 0; ks < 4; ++ks) {
            uint32_t cp = colPart[ks];
#pragma unroll
            for (int mt = 0; mt < 2; ++mt) {
                // A m16k16 fragment: regs map directly a0..a3
                asm volatile("ldmatrix.sync.aligned.m8n8.x4.shared.b16 {%0,%1,%2,%3}, [%4];"
                             : "=r"(aF[mt][0]), "=r"(aF[mt][1]),
                               "=r"(aF[mt][2]), "=r"(aF[mt][3])
                             : "r"(sB + aRow[mt] + cp));
            }
#pragma unroll
            for (int g = 0; g < 2; ++g) {
                // B: two n8k16 fragments per x4: {r0,r2} and {r1,r3}
                uint32_t r0, r1, r2, r3;
                asm volatile("ldmatrix.sync.aligned.m8n8.x4.shared.b16 {%0,%1,%2,%3}, [%4];"
                             : "=r"(r0), "=r"(r1), "=r"(r2), "=r"(r3)
                             : "r"(sB + bRow[g] + cp));
                bF[g * 2][0]     = r0; bF[g * 2][1]     = r2;
                bF[g * 2 + 1][0] = r1; bF[g * 2 + 1][1] = r3;
            }
#pragma unroll
            for (int mt = 0; mt < 2; ++mt)
#pragma unroll
                for (int nt = 0; nt < 4; ++nt)
                    mma_f16(acc[mt][nt], aF[mt], bF[nt]);
        }
    }

    // ---- epilogue: bias + STG.64 (same acc layout as 1688) ----
    const int col0 = n0 + warpN * 32 + 2 * (lane & 3);
    float2 bv[4];
#pragma unroll
    for (int nt = 0; nt < 4; ++nt)
        bv[nt] = *(const float2*)(bias + col0 + nt * 8);

    const int row0 = m0 + warpM * 32 + (lane >> 2);
#pragma unroll
    for (int mt = 0; mt < 2; ++mt) {
        int r = row0 + mt * 16;
#pragma unroll
        for (int nt = 0; nt < 4; ++nt) {
            int cc = col0 + nt * 8;
            float2 v0, v1;
            v0.x = acc[mt][nt][0] + bv[nt].x;
            v0.y = acc[mt][nt][1] + bv[nt].y;
            v1.x = acc[mt][nt][2] + bv[nt].x;
            v1.y = acc[mt][nt][3] + bv[nt].y;
            *(float2*)(C + (size_t)r * N + cc)       = v0;
            *(float2*)(C + (size_t)(r + 8) * N + cc) = v1;
        }
    }
}

// ---------------------------------------------------------------------------
// Block attention: one warp per (b, h, block). BS=4, d=64.
// Reads f32 qkv, writes fp16 o (feeds proj GEMM directly).
// ---------------------------------------------------------------------------
__global__ __launch_bounds__(256)
void block_attn_kernel(const float* __restrict__ qkv, __half* __restrict__ o)
{
    const int gwarp = (blockIdx.x * blockDim.x + threadIdx.x) >> 5;
    const int lane  = threadIdx.x & 31;

    const int nb = gwarp & 1023;
    const int bh = gwarp >> 10;
    const int h  = bh & 15;
    const int b  = bh >> 4;
    const int l0 = nb * BLK;

    const size_t rowBase = ((size_t)(b * Ll + l0)) * NQKV + h * 192;

    float2 q[4], k[4], v[4];
#pragma unroll
    for (int i = 0; i < 4; ++i) {
        const float* p = qkv + rowBase + (size_t)i * NQKV + 2 * lane;
        q[i] = *(const float2*)(p);
        k[i] = *(const float2*)(p + 64);
        v[i] = *(const float2*)(p + 128);
    }

    float s[4][4];
#pragma unroll
    for (int i = 0; i < 4; ++i)
#pragma unroll
        for (int j = 0; j < 4; ++j)
            s[i][j] = fmaf(q[i].y, k[j].y, q[i].x * k[j].x);

#pragma unroll
    for (int i = 0; i < 4; ++i)
#pragma unroll
        for (int j = 0; j < 4; ++j)
#pragma unroll
            for (int off = 16; off > 0; off >>= 1)
                s[i][j] += __shfl_xor_sync(0xffffffffu, s[i][j], off);

    const float scale = 0.125f;
    const size_t obase = ((size_t)(b * Ll + l0)) * Dd + h * HDIM + 2 * lane;
#pragma unroll
    for (int i = 0; i < 4; ++i) {
        float t0 = s[i][0] * scale, t1 = s[i][1] * scale;
        float t2 = s[i][2] * scale, t3 = s[i][3] * scale;
        float m = fmaxf(fmaxf(t0, t1), fmaxf(t2, t3));
        float e0 = __expf(t0 - m), e1 = __expf(t1 - m);
        float e2 = __expf(t2 - m), e3 = __expf(t3 - m);
        float inv = 1.0f / (e0 + e1 + e2 + e3);
        float p0 = e0 * inv, p1 = e1 * inv, p2 = e2 * inv, p3 = e3 * inv;
        float ox = p0 * v[0].x; ox = fmaf(p1, v[1].x, ox);
        ox = fmaf(p2, v[2].x, ox); ox = fmaf(p3, v[3].x, ox);
        float oy = p0 * v[0].y; oy = fmaf(p1, v[1].y, oy);
        oy = fmaf(p2, v[2].y, oy); oy = fmaf(p3, v[3].y, oy);
        __half2 hv = __floats2half2_rn(ox, oy);
        *(__half2*)(o + obase + (size_t)i * Dd) = hv;
    }
}

// ---------------------------------------------------------------------------
extern "C" void kernel_launch(void* const* d_in, const int* in_sizes, int n_in,
                              void* d_out, int out_size)
{
    const float* x     = (const float*)d_in[0];
    const float* Wqkv  = (const float*)d_in[1];
    const float* bqkv  = (const float*)d_in[2];
    const float* Wproj = (const float*)d_in[3];
    const float* bproj = (const float*)d_in[4];
    float* out = (float*)d_out;

    float *qkv;
    __half *oh, *xh, *wqh, *wph;
    cudaGetSymbolAddress((void**)&qkv, g_qkv);
    cudaGetSymbolAddress((void**)&oh,  g_oh);
    cudaGetSymbolAddress((void**)&xh,  g_xh);
    cudaGetSymbolAddress((void**)&wqh, g_wqh);
    cudaGetSymbolAddress((void**)&wph, g_wph);

    cudaFuncSetAttribute(gemm_hmma_kernel,
                         cudaFuncAttributeMaxDynamicSharedMemorySize, GEMM_SMEM);

    // 0) x -> fp16; weights -> transposed fp16 (Wt[N][K])
    f2h_kernel<<<8192, 256>>>((const float4*)x, (uint2*)xh, MTOT * Dd / 4);
    {
        dim3 g1(NQKV / 32, Dd / 32);
        transpose_h_kernel<<<g1, 256>>>(Wqkv, wqh, Dd, NQKV);
        dim3 g2(Dd / 32, Dd / 32);
        transpose_h_kernel<<<g2, 256>>>(Wproj, wph, Dd, Dd);
    }

    // 1) qkv = x @ W_qkv + b_qkv   (32768 x 3072 x 1024), fp16 in / f32 out
    {
        dim3 grid(NQKV / 64, MTOT / 128);
        gemm_hmma_kernel<<<grid, 256, GEMM_SMEM>>>(xh, wqh, bqkv, qkv, NQKV, Dd);
    }

    // 2) block attention (f32 in, fp16 out)
    {
        int nwarps = Bb * Hh * (Ll / BLK);
        block_attn_kernel<<<nwarps / 8, 256>>>(qkv, oh);
    }

    // 3) out = o @ W_proj + b_proj  (32768 x 1024 x 1024)
    {
        dim3 grid(Dd / 64, MTOT / 128);
        gemm_hmma_kernel<<<grid, 256, GEMM_SMEM>>>(oh, wph, bproj, out, Dd, Dd);
    }
}